// round 4
// baseline (speedup 1.0000x reference)
#include <cuda_runtime.h>
#include <cstdint>

#define Bsz   32
#define C_INc 128
#define Lseq  4096
#define C_OUTc 256
#define NP    64
#define PATCHw 64
#define PKw   9
#define PADw  4

#define O_TILE 64
#define L_TILE 128
#define CC     8

typedef unsigned long long u64;

// Scratch (cudaMalloc is banned; __device__ globals are the sanctioned path)
__device__ float g_sa[(size_t)Bsz * C_INc * Lseq];     // 64 MB intermediate
__device__ float g_wt[C_INc * PKw * C_OUTc];           // weights as [c][k][o]

// ---------------------------------------------------------------------------
// f32x2 packed-math helpers (Blackwell dual-FP32 path, PTX-only)
// ---------------------------------------------------------------------------
__device__ __forceinline__ u64 packbc(float v) {
    u64 r; asm("mov.b64 %0, {%1, %1};" : "=l"(r) : "f"(v)); return r;
}
__device__ __forceinline__ u64 ffma2(u64 a, u64 b, u64 c) {
    u64 d; asm("fma.rn.f32x2 %0, %1, %2, %3;" : "=l"(d) : "l"(a), "l"(b), "l"(c));
    return d;
}
__device__ __forceinline__ float2 unpack2(u64 v) {
    float2 f; asm("mov.b64 {%0, %1}, %2;" : "=f"(f.x), "=f"(f.y) : "l"(v));
    return f;
}
__device__ __forceinline__ float selu_f(float x) {
    return 1.0507009873554805f * (x > 0.f ? x : 1.6732632423543772f * expm1f(x));
}

// ---------------------------------------------------------------------------
// Weight transpose: of[o][c][k] -> g_wt[(c*9+k)*256 + o]
// ---------------------------------------------------------------------------
__global__ void k_transpose_w(const float* __restrict__ of) {
    int idx = blockIdx.x * blockDim.x + threadIdx.x;
    if (idx < C_OUTc * C_INc * PKw) {
        int o = idx / (C_INc * PKw);
        int r = idx - o * (C_INc * PKw);
        int c = r / PKw;
        int k = r - c * PKw;
        g_wt[(c * PKw + k) * C_OUTc + o] = of[idx];
    }
}

// ---------------------------------------------------------------------------
// Stage 1: per-patch depthwise conv with per-patch zero padding.
// One block per (b,c) row of 4096.
// ---------------------------------------------------------------------------
__global__ void k_stage1(const float* __restrict__ x, const float* __restrict__ pf) {
    __shared__ float xs[Lseq];
    __shared__ float pfs[NP * PKw];
    int bc = blockIdx.x;                 // b*C_IN + c
    int c  = bc & (C_INc - 1);
    const float* xrow = x + (size_t)bc * Lseq;
    for (int i = threadIdx.x; i < Lseq; i += blockDim.x) xs[i] = xrow[i];
    const float* pfrow = pf + (size_t)c * NP * PKw;
    for (int i = threadIdx.x; i < NP * PKw; i += blockDim.x) pfs[i] = pfrow[i];
    __syncthreads();
    float* sarow = g_sa + (size_t)bc * Lseq;
    for (int l = threadIdx.x; l < Lseq; l += blockDim.x) {
        int u    = l & (PATCHw - 1);
        int base = l - u;
        int p    = l >> 6;
        float acc = 0.f;
        #pragma unroll
        for (int k = 0; k < PKw; ++k) {
            int idx = u + k - PADw;
            if ((unsigned)idx < (unsigned)PATCHw)
                acc = fmaf(xs[base + idx], pfs[p * PKw + k], acc);
        }
        sarow[l] = acc;
    }
}

// ---------------------------------------------------------------------------
// Stage 2: dense conv as tiled "GEMM" with f32x2 packed FMA + fused SELU.
// Block tile: 64 o x 128 l, one batch. Thread tile: 8 o x 4 l.
// Grid: x = o-tile (fastest) so the 4 CTAs sharing one sa tile are
// launch-adjacent -> sa re-reads hit L2. y = l-tile, z = batch.
// ---------------------------------------------------------------------------
__global__ __launch_bounds__(256) void k_stage2(float* __restrict__ out) {
    __shared__ __align__(16) float ws[CC][PKw][O_TILE];    // 18432 B
    __shared__ __align__(16) float ss[CC][L_TILE + 8];     //  4352 B

    const int o0 = blockIdx.x * O_TILE;
    const int l0 = blockIdx.y * L_TILE;
    const int b  = blockIdx.z;
    const int tx = threadIdx.x;
    const int lg = tx & 31;    // position group: l = l0 + lg*4 + j
    const int og = tx >> 5;    // output group:  o = o0 + og*8 + p*2 + {0,1}

    u64 acc[4][4];
    #pragma unroll
    for (int p = 0; p < 4; ++p)
        #pragma unroll
        for (int j = 0; j < 4; ++j) acc[p][j] = 0ULL;

    for (int cb = 0; cb < C_INc; cb += CC) {
        // ---- stage weights tile: ws[c][k][o], o contiguous (coalesced from g_wt)
        for (int i = tx; i < CC * PKw * O_TILE; i += 256) {
            int c = i / (PKw * O_TILE);
            int r = i - c * (PKw * O_TILE);
            int k = r >> 6;
            int o = r & 63;
            ws[c][k][o] = g_wt[((cb + c) * PKw + k) * C_OUTc + o0 + o];
        }
        // ---- stage sa tile with +-4 halo, zero-filled at sequence edges
        for (int i = tx; i < CC * (L_TILE + 8); i += 256) {
            int c = i / (L_TILE + 8);
            int j = i - c * (L_TILE + 8);
            int l = l0 - PADw + j;
            float v = 0.f;
            if ((unsigned)l < (unsigned)Lseq)
                v = g_sa[(size_t)(b * C_INc + cb + c) * Lseq + l];
            ss[c][j] = v;
        }
        __syncthreads();

        #pragma unroll
        for (int c = 0; c < CC; ++c) {
            // 12-float s window via 3 conflict-free LDS.128
            const float4 v0 = *reinterpret_cast<const float4*>(&ss[c][lg * 4]);
            const float4 v1 = *reinterpret_cast<const float4*>(&ss[c][lg * 4 + 4]);
            const float4 v2 = *reinterpret_cast<const float4*>(&ss[c][lg * 4 + 8]);
            u64 sb[12];
            sb[0] = packbc(v0.x); sb[1] = packbc(v0.y); sb[2]  = packbc(v0.z); sb[3]  = packbc(v0.w);
            sb[4] = packbc(v1.x); sb[5] = packbc(v1.y); sb[6]  = packbc(v1.z); sb[7]  = packbc(v1.w);
            sb[8] = packbc(v2.x); sb[9] = packbc(v2.y); sb[10] = packbc(v2.z); sb[11] = packbc(v2.w);
            #pragma unroll
            for (int k = 0; k < PKw; ++k) {
                const u64* wrow = reinterpret_cast<const u64*>(&ws[c][k][og * 8]);
                const u64 w0 = wrow[0], w1 = wrow[1], w2 = wrow[2], w3 = wrow[3];
                #pragma unroll
                for (int j = 0; j < 4; ++j) {
                    const u64 s2 = sb[j + k];
                    acc[0][j] = ffma2(w0, s2, acc[0][j]);
                    acc[1][j] = ffma2(w1, s2, acc[1][j]);
                    acc[2][j] = ffma2(w2, s2, acc[2][j]);
                    acc[3][j] = ffma2(w3, s2, acc[3][j]);
                }
            }
        }
        __syncthreads();
    }

    // ---- epilogue: SELU + vectorized store
    const int lbase = l0 + lg * 4;
    #pragma unroll
    for (int p = 0; p < 4; ++p) {
        float2 a0 = unpack2(acc[p][0]);
        float2 a1 = unpack2(acc[p][1]);
        float2 a2 = unpack2(acc[p][2]);
        float2 a3 = unpack2(acc[p][3]);
        float4 r0 = make_float4(selu_f(a0.x), selu_f(a1.x), selu_f(a2.x), selu_f(a3.x));
        float4 r1 = make_float4(selu_f(a0.y), selu_f(a1.y), selu_f(a2.y), selu_f(a3.y));
        int o = o0 + og * 8 + p * 2;
        *reinterpret_cast<float4*>(&out[((size_t)b * C_OUTc + o)     * Lseq + lbase]) = r0;
        *reinterpret_cast<float4*>(&out[((size_t)b * C_OUTc + o + 1) * Lseq + lbase]) = r1;
    }
}

// ---------------------------------------------------------------------------
extern "C" void kernel_launch(void* const* d_in, const int* in_sizes, int n_in,
                              void* d_out, int out_size) {
    (void)in_sizes; (void)n_in; (void)out_size;
    const float* x  = (const float*)d_in[0];   // (32,128,4096)
    const float* pf = (const float*)d_in[1];   // (128,64,1,9)
    const float* of = (const float*)d_in[2];   // (256,128,9)
    float* out = (float*)d_out;                // (32,256,4096)

    k_transpose_w<<<(C_OUTc * C_INc * PKw + 255) / 256, 256>>>(of);
    k_stage1<<<Bsz * C_INc, 256>>>(x, pf);
    dim3 g2(C_OUTc / O_TILE, Lseq / L_TILE, Bsz);
    k_stage2<<<g2, 256>>>(out);
}

// round 6
// speedup vs baseline: 2.7597x; 2.7597x over previous
#include <cuda_runtime.h>
#include <cstdint>

#define Bsz    32
#define C_INc  128
#define Lseq   4096
#define C_OUTc 256
#define PKw    9
#define PADw   4

#define M_TILE 128     // l positions per CTA
#define N_TILE 128     // o channels per CTA
#define NCH    36      // K chunks: 9 taps x 4 c-subchunks of 32

typedef unsigned long long u64;

// __device__ globals: sanctioned scratch (no cudaMalloc allowed)
__device__ float g_saT[(size_t)Bsz * Lseq * C_INc];    // [b][l][c], tf32-rounded
__device__ float g_wB [(size_t)PKw * C_INc * C_OUTc];  // [kk][c][o], tf32-rounded

// ---------------------------------------------------------------------------
__device__ __forceinline__ uint32_t smem_u32(const void* p) {
    uint32_t a;
    asm("{ .reg .u64 t; cvta.to.shared.u64 t, %1; cvt.u32.u64 %0, t; }" : "=r"(a) : "l"(p));
    return a;
}
__device__ __forceinline__ uint32_t f2tf32(float x) {
    uint32_t u; asm("cvt.rn.tf32.f32 %0, %1;" : "=r"(u) : "f"(x)); return u;
}
__device__ __forceinline__ float selu_f(float x) {
    return 1.0507009873554805f * (x > 0.f ? x : 1.6732632423543772f * expm1f(x));
}
__device__ __forceinline__ void cp16(uint32_t dst, const float* src) {
    asm volatile("{ .reg .u64 g; cvta.to.global.u64 g, %1;"
                 "  cp.async.ca.shared.global [%0], [g], 16; }"
                 :: "r"(dst), "l"(src) : "memory");
}
__device__ __forceinline__ void mma_tf32(float* c, const uint32_t* a, const uint32_t* b) {
    asm volatile(
        "mma.sync.aligned.m16n8k8.row.col.f32.tf32.tf32.f32 "
        "{%0,%1,%2,%3}, {%4,%5,%6,%7}, {%8,%9}, {%0,%1,%2,%3};"
        : "+f"(c[0]), "+f"(c[1]), "+f"(c[2]), "+f"(c[3])
        : "r"(a[0]), "r"(a[1]), "r"(a[2]), "r"(a[3]), "r"(b[0]), "r"(b[1]));
}

// ---------------------------------------------------------------------------
// Weight prep: g_wB[kk][c][o] = tf32_rn(of[o][c][kk])
// ---------------------------------------------------------------------------
__global__ void k_wprep(const float* __restrict__ of) {
    int idx = blockIdx.x * 256 + threadIdx.x;         // [kk][c][o]
    if (idx < PKw * C_INc * C_OUTc) {
        int o  = idx & 255;
        int t  = idx >> 8;
        int c  = t & 127;
        int kk = t >> 7;
        ((uint32_t*)g_wB)[idx] = f2tf32(of[(o * C_INc + c) * PKw + kk]);
    }
}

// ---------------------------------------------------------------------------
// Stage 1: per-patch depthwise conv -> g_saT[b][l][c] (transposed, tf32-rounded)
// Block: (l-tile 128 = 2 patches, b). 128 threads, c in chunks of 32.
// ---------------------------------------------------------------------------
__global__ __launch_bounds__(128) void k_stage1(const float* __restrict__ x,
                                                const float* __restrict__ pf) {
    __shared__ float x_s[32][132];       // [c][l]
    __shared__ uint32_t sa_s[128][36];   // [l][c] tf32 bits
    __shared__ float pfs[32][2][PKw];

    const int l0 = blockIdx.x * 128;
    const int b  = blockIdx.y;
    const int tx = threadIdx.x;          // = l within tile
    const int p0 = l0 >> 6;

    for (int cb = 0; cb < C_INc; cb += 32) {
        for (int it = 0; it < 8; ++it) {
            int i = tx + (it << 7);              // 0..1023 float4s
            int c = i >> 5, seg = i & 31;
            *reinterpret_cast<float4*>(&x_s[c][seg * 4]) =
                *reinterpret_cast<const float4*>(&x[((size_t)(b * C_INc + cb + c)) * Lseq + l0 + seg * 4]);
        }
        for (int i = tx; i < 32 * 2 * PKw; i += 128) {
            int c = i / (2 * PKw), r = i % (2 * PKw);
            int p = r / PKw, k = r % PKw;
            pfs[c][p][k] = pf[((size_t)(cb + c) * 64 + p0 + p) * PKw + k];
        }
        __syncthreads();

        const int l  = tx;
        const int u  = l & 63;
        const int pl = l >> 6;
        #pragma unroll 4
        for (int c = 0; c < 32; ++c) {
            float acc = 0.f;
            #pragma unroll
            for (int k = 0; k < PKw; ++k) {
                int v = u + k - PADw;
                if ((unsigned)v < 64u)
                    acc = fmaf(x_s[c][l + k - PADw], pfs[c][pl][k], acc);
            }
            sa_s[l][c] = f2tf32(acc);
        }
        __syncthreads();

        for (int it = 0; it < 8; ++it) {
            int i = tx + (it << 7);              // 0..1023
            int row = i >> 3, seg = i & 7;
            float4 v = *reinterpret_cast<const float4*>(&sa_s[row][seg * 4]);
            *reinterpret_cast<float4*>(&g_saT[((size_t)b * Lseq + l0 + row) * C_INc + cb + seg * 4]) = v;
        }
        __syncthreads();
    }
}

// ---------------------------------------------------------------------------
// Stage 2: tf32 mma.sync implicit GEMM + fused SELU (sm_100-baseline path).
// CTA: 128 l x 128 o, 256 threads = 8 warps (warp grid 4m x 2n, warp tile 32x64).
// A = sa rows l0-4..l0+131 resident in smem (tap shift kk = row offset).
// B = weight chunks [32 c][128 o] via cp.async double buffer.
// ---------------------------------------------------------------------------
#define A_STRIDE 132
#define A_BYTES  (136 * A_STRIDE * 4)          // 71808
#define W_STRIDE 132
#define W_BYTES  (32 * W_STRIDE * 4)           // 16896
#define OFF_W0   A_BYTES
#define OFF_W1   (A_BYTES + W_BYTES)
#define SMEM_SZ  (A_BYTES + 2 * W_BYTES)       // 105600

__global__ __launch_bounds__(256) void k_stage2(float* __restrict__ out) {
    extern __shared__ __align__(16) char smem[];
    float* a_s = reinterpret_cast<float*>(smem);
    const uint32_t sbase = smem_u32(smem);

    const int l0 = blockIdx.x * M_TILE;
    const int o0 = blockIdx.y * N_TILE;
    const int b  = blockIdx.z;
    const int tid  = threadIdx.x;
    const int lane = tid & 31, wid = tid >> 5;
    const int wm = wid & 3;        // m quarter (32 rows)
    const int wn = wid >> 2;       // n half (64 cols)

    // ---- stage A: rows l0-4 .. l0+131 of g_saT[b][.][c], zero-filled OOB
    for (int it = 0; it < 17; ++it) {
        int i = tid + (it << 8);               // 0..4351
        int row = i >> 5, c4 = i & 31;
        int gl = l0 - PADw + row;
        float4 v = make_float4(0.f, 0.f, 0.f, 0.f);
        if ((unsigned)gl < (unsigned)Lseq)
            v = *reinterpret_cast<const float4*>(&g_saT[((size_t)b * Lseq + gl) * C_INc + c4 * 4]);
        *reinterpret_cast<float4*>(&a_s[row * A_STRIDE + c4 * 4]) = v;
    }

    // ---- B chunk loader (cp.async, 16B)
    auto load_w = [&](int ch, int buf) {
        int kk = ch >> 2, c0 = (ch & 3) << 5;
        const float* src = &g_wB[((size_t)(kk * C_INc + c0)) * C_OUTc + o0];
        uint32_t dbase = sbase + (buf ? OFF_W1 : OFF_W0);
        #pragma unroll
        for (int it = 0; it < 4; ++it) {
            int i = tid + (it << 8);           // 0..1023
            int cr = i >> 5, s = i & 31;
            cp16(dbase + (uint32_t)(cr * W_STRIDE + s * 4) * 4,
                 src + (size_t)cr * C_OUTc + s * 4);
        }
        asm volatile("cp.async.commit_group;" ::: "memory");
    };

    float acc[2][8][4];
    #pragma unroll
    for (int mt = 0; mt < 2; ++mt)
        #pragma unroll
        for (int nt = 0; nt < 8; ++nt)
            #pragma unroll
            for (int r = 0; r < 4; ++r) acc[mt][nt][r] = 0.f;

    const uint32_t* au = reinterpret_cast<const uint32_t*>(a_s);

    load_w(0, 0);
    for (int ch = 0; ch < NCH; ++ch) {
        const int buf = ch & 1;
        if (ch + 1 < NCH) {
            load_w(ch + 1, buf ^ 1);
            asm volatile("cp.async.wait_group 1;" ::: "memory");
        } else {
            asm volatile("cp.async.wait_group 0;" ::: "memory");
        }
        __syncthreads();

        const int kk = ch >> 2, c0 = (ch & 3) << 5;
        const uint32_t* wu = reinterpret_cast<const uint32_t*>(smem + (buf ? OFF_W1 : OFF_W0));
        const int arow = wm * 32 + (lane >> 2) + kk;   // +4 halo already in row index
        const int wcol = wn * 64 + (lane >> 2);

        #pragma unroll
        for (int kb = 0; kb < 4; ++kb) {
            const int kcol = c0 + kb * 8 + (lane & 3);
            uint32_t a[2][4];
            #pragma unroll
            for (int mt = 0; mt < 2; ++mt) {
                int r = arow + mt * 16;
                a[mt][0] = au[r * A_STRIDE + kcol];
                a[mt][1] = au[(r + 8) * A_STRIDE + kcol];
                a[mt][2] = au[r * A_STRIDE + kcol + 4];
                a[mt][3] = au[(r + 8) * A_STRIDE + kcol + 4];
            }
            const int wrow = kb * 8 + (lane & 3);
            uint32_t bb[8][2];
            #pragma unroll
            for (int nt = 0; nt < 8; ++nt) {
                bb[nt][0] = wu[wrow * W_STRIDE + wcol + nt * 8];
                bb[nt][1] = wu[(wrow + 4) * W_STRIDE + wcol + nt * 8];
            }
            #pragma unroll
            for (int mt = 0; mt < 2; ++mt)
                #pragma unroll
                for (int nt = 0; nt < 8; ++nt)
                    mma_tf32(acc[mt][nt], a[mt], bb[nt]);
        }
        __syncthreads();
    }

    // ---- epilogue: transpose through smem (reuse A region) -> coalesced SELU stores
    float* o_s = a_s;                          // [128 o][132 l] = 67584 B <= A region
    #pragma unroll
    for (int mt = 0; mt < 2; ++mt)
        #pragma unroll
        for (int nt = 0; nt < 8; ++nt) {
            int m = wm * 32 + mt * 16 + (lane >> 2);
            int o = wn * 64 + nt * 8 + 2 * (lane & 3);
            o_s[o * A_STRIDE + m]           = acc[mt][nt][0];
            o_s[(o + 1) * A_STRIDE + m]     = acc[mt][nt][1];
            o_s[o * A_STRIDE + m + 8]       = acc[mt][nt][2];
            o_s[(o + 1) * A_STRIDE + m + 8] = acc[mt][nt][3];
        }
    __syncthreads();

    for (int it = 0; it < 16; ++it) {
        int i = tid + (it << 8);               // 0..4095
        int ol = i >> 5, s = i & 31;
        float4 v = *reinterpret_cast<const float4*>(&o_s[ol * A_STRIDE + s * 4]);
        v.x = selu_f(v.x); v.y = selu_f(v.y); v.z = selu_f(v.z); v.w = selu_f(v.w);
        *reinterpret_cast<float4*>(&out[((size_t)(b * C_OUTc + o0 + ol)) * Lseq + l0 + s * 4]) = v;
    }
}

// ---------------------------------------------------------------------------
extern "C" void kernel_launch(void* const* d_in, const int* in_sizes, int n_in,
                              void* d_out, int out_size) {
    (void)in_sizes; (void)n_in; (void)out_size;
    const float* x  = (const float*)d_in[0];   // (32,128,4096)
    const float* pf = (const float*)d_in[1];   // (128,64,1,9)
    const float* of = (const float*)d_in[2];   // (256,128,9)
    float* out = (float*)d_out;                // (32,256,4096)

    cudaFuncSetAttribute(k_stage2, cudaFuncAttributeMaxDynamicSharedMemorySize, SMEM_SZ);

    k_wprep<<<(PKw * C_INc * C_OUTc + 255) / 256, 256>>>(of);
    k_stage1<<<dim3(Lseq / 128, Bsz), 128>>>(x, pf);
    k_stage2<<<dim3(Lseq / M_TILE, C_OUTc / N_TILE, Bsz), 256, SMEM_SZ>>>(out);
}